// round 4
// baseline (speedup 1.0000x reference)
#include <cuda_runtime.h>
#include <cuda_bf16.h>

#define N_NODES 50000
#define N_EDGES 800000
#define NUM_GRAPHS 256
#define D 64
#define EPS 1e-5f

// ---------------- scratch (device globals; no allocation) ----------------
__device__ float g_xw[N_NODES * D];
__device__ float g_agg[N_NODES * D];
__device__ float g_deg[N_NODES];
__device__ float g_dinv[N_NODES];
__device__ float g_pooled[NUM_GRAPHS * D];
__device__ float g_cnt[NUM_GRAPHS];

// ---------------- small utility kernels ----------------
__global__ void k_deg_init() {
    int i = blockIdx.x * blockDim.x + threadIdx.x;
    if (i < N_NODES) g_deg[i] = 1.0f;  // self-loop
}

__global__ void k_deg_count(const int* __restrict__ col) {
    int e = blockIdx.x * blockDim.x + threadIdx.x;
    if (e < N_EDGES) atomicAdd(&g_deg[col[e]], 1.0f);
}

__global__ void k_dinv() {
    int i = blockIdx.x * blockDim.x + threadIdx.x;
    if (i < N_NODES) g_dinv[i] = rsqrtf(g_deg[i]);
}

__global__ void k_zero_agg() {
    int i = blockIdx.x * blockDim.x + threadIdx.x;
    if (i < N_NODES * D / 4) ((float4*)g_agg)[i] = make_float4(0.f, 0.f, 0.f, 0.f);
}

__global__ void k_zero_pool() {
    int i = blockIdx.x * blockDim.x + threadIdx.x;
    if (i < NUM_GRAPHS * D) g_pooled[i] = 0.0f;
    if (i < NUM_GRAPHS) g_cnt[i] = 0.0f;
}

// ---------------- GEMM: C[n,64] = A[n,64] @ W[64,64] ----------------
// 256 threads/block, 64 rows/block. Each thread: 1 row x 16 cols in registers.
// A row via LDG.128 (L1-cached, 4 threads share a row), W via LDS.128.
__global__ void k_gemm64(const float* __restrict__ A,
                         const float* __restrict__ W,
                         float* __restrict__ C) {
    __shared__ float4 Ws[64][16];  // W[k][c], row k = 16 float4s
    int tid = threadIdx.x;
    int row0 = blockIdx.x * 64;

    #pragma unroll
    for (int i = tid; i < 1024; i += 256)
        Ws[i >> 4][i & 15] = ((const float4*)W)[i];
    __syncthreads();

    int r = row0 + (tid >> 2);
    bool valid = (r < N_NODES);
    int rr = valid ? r : 0;
    int c4 = (tid & 3) * 4;  // float4-group base: cols [ (tid&3)*16, +16 )

    float4 acc0 = {0,0,0,0}, acc1 = {0,0,0,0}, acc2 = {0,0,0,0}, acc3 = {0,0,0,0};
    const float4* Arow = (const float4*)(A + rr * 64);

    #pragma unroll
    for (int kk = 0; kk < 16; kk++) {
        float4 a = __ldg(&Arow[kk]);
        #pragma unroll
        for (int q = 0; q < 4; q++) {
            float av = (q == 0) ? a.x : (q == 1) ? a.y : (q == 2) ? a.z : a.w;
            int k = kk * 4 + q;
            float4 w0 = Ws[k][c4 + 0];
            float4 w1 = Ws[k][c4 + 1];
            float4 w2 = Ws[k][c4 + 2];
            float4 w3 = Ws[k][c4 + 3];
            acc0.x = fmaf(av, w0.x, acc0.x); acc0.y = fmaf(av, w0.y, acc0.y);
            acc0.z = fmaf(av, w0.z, acc0.z); acc0.w = fmaf(av, w0.w, acc0.w);
            acc1.x = fmaf(av, w1.x, acc1.x); acc1.y = fmaf(av, w1.y, acc1.y);
            acc1.z = fmaf(av, w1.z, acc1.z); acc1.w = fmaf(av, w1.w, acc1.w);
            acc2.x = fmaf(av, w2.x, acc2.x); acc2.y = fmaf(av, w2.y, acc2.y);
            acc2.z = fmaf(av, w2.z, acc2.z); acc2.w = fmaf(av, w2.w, acc2.w);
            acc3.x = fmaf(av, w3.x, acc3.x); acc3.y = fmaf(av, w3.y, acc3.y);
            acc3.z = fmaf(av, w3.z, acc3.z); acc3.w = fmaf(av, w3.w, acc3.w);
        }
    }

    if (valid) {
        float4* Crow = (float4*)(C + rr * 64) + c4;
        Crow[0] = acc0; Crow[1] = acc1; Crow[2] = acc2; Crow[3] = acc3;
    }
}

// ---------------- edge scatter: agg[col] += dinv[row]*dinv[col]*xw[row] ----------------
// 16 threads per edge; each does one float4 gather + one red.v4.f32.
__global__ void k_scatter(const int* __restrict__ row,
                          const int* __restrict__ col) {
    long long gt = (long long)blockIdx.x * blockDim.x + threadIdx.x;
    int e = (int)(gt >> 4);
    if (e >= N_EDGES) return;
    int t = (int)gt & 15;
    int r = __ldg(&row[e]);
    int c = __ldg(&col[e]);
    float s = g_dinv[r] * g_dinv[c];
    float4 v = __ldg((const float4*)(g_xw + r * 64) + t);
    v.x *= s; v.y *= s; v.z *= s; v.w *= s;
    float* dst = g_agg + c * 64 + t * 4;
    asm volatile("red.global.add.v4.f32 [%0], {%1, %2, %3, %4};"
                 :: "l"(dst), "f"(v.x), "f"(v.y), "f"(v.z), "f"(v.w)
                 : "memory");
}

// ---------------- epilogue: self-loop + bias, BN, ReLU (in-place on g_agg) ----------------
__global__ void k_epilogue(const float* __restrict__ b,
                           const float* __restrict__ bg,
                           const float* __restrict__ bb,
                           const float* __restrict__ bm,
                           const float* __restrict__ bv) {
    int i = blockIdx.x * blockDim.x + threadIdx.x;  // float4 index
    if (i >= N_NODES * D / 4) return;
    int node = i >> 4;
    int j = (i & 15) * 4;
    float di = g_dinv[node];
    float s2 = di * di;
    float4 agg = ((const float4*)g_agg)[i];
    float4 xw  = ((const float4*)g_xw)[i];
    float4 bj  = *(const float4*)(b + j);
    float4 mg  = *(const float4*)(bm + j);
    float4 vg  = *(const float4*)(bv + j);
    float4 gg  = *(const float4*)(bg + j);
    float4 bbj = *(const float4*)(bb + j);
    float4 o;
    o.x = fmaxf((agg.x + s2 * xw.x + bj.x - mg.x) * rsqrtf(vg.x + EPS) * gg.x + bbj.x, 0.f);
    o.y = fmaxf((agg.y + s2 * xw.y + bj.y - mg.y) * rsqrtf(vg.y + EPS) * gg.y + bbj.y, 0.f);
    o.z = fmaxf((agg.z + s2 * xw.z + bj.z - mg.z) * rsqrtf(vg.z + EPS) * gg.z + bbj.z, 0.f);
    o.w = fmaxf((agg.w + s2 * xw.w + bj.w - mg.w) * rsqrtf(vg.w + EPS) * gg.w + bbj.w, 0.f);
    ((float4*)g_agg)[i] = o;
}

// ---------------- global mean pool: run-length segment reduce (batch sorted) ----------------
#define POOL_NODES 200
__global__ void k_pool(const int* __restrict__ batch) {
    int c = threadIdx.x;                 // 64 threads = one column each
    int n0 = blockIdx.x * POOL_NODES;
    int n1 = n0 + POOL_NODES; if (n1 > N_NODES) n1 = N_NODES;
    if (n0 >= N_NODES) return;
    int cur = __ldg(&batch[n0]);
    float acc = 0.f;
    float cnt = 0.f;
    for (int n = n0; n < n1; n++) {
        int bkt = __ldg(&batch[n]);
        if (bkt != cur) {
            atomicAdd(&g_pooled[cur * D + c], acc);
            if (c == 0) atomicAdd(&g_cnt[cur], cnt);
            cur = bkt; acc = 0.f; cnt = 0.f;
        }
        acc += g_agg[n * D + c];
        cnt += 1.f;
    }
    atomicAdd(&g_pooled[cur * D + c], acc);
    if (c == 0) atomicAdd(&g_cnt[cur], cnt);
}

// ---------------- MLP head: one block per graph ----------------
__global__ void k_mlp(const float* __restrict__ hW1, const float* __restrict__ hb1,
                      const float* __restrict__ hg1, const float* __restrict__ hbb1,
                      const float* __restrict__ hm1, const float* __restrict__ hv1,
                      const float* __restrict__ hW2, const float* __restrict__ hb2,
                      const float* __restrict__ hg2, const float* __restrict__ hbb2,
                      const float* __restrict__ hm2, const float* __restrict__ hv2,
                      const float* __restrict__ hW3, const float* __restrict__ hb3,
                      const float* __restrict__ hW4, const float* __restrict__ hb4,
                      float* __restrict__ out) {
    __shared__ float p[64];
    __shared__ float z1[256];
    __shared__ float z2[128];
    __shared__ float z3[64];
    int g = blockIdx.x;
    int tid = threadIdx.x;
    if (tid < 64) {
        float c = fmaxf(g_cnt[g], 1.0f);
        p[tid] = g_pooled[g * D + tid] / c;
    }
    __syncthreads();
    {
        float acc = hb1[tid];
        #pragma unroll
        for (int k = 0; k < 64; k++) acc = fmaf(p[k], hW1[k * 256 + tid], acc);
        acc = (acc - hm1[tid]) * rsqrtf(hv1[tid] + EPS) * hg1[tid] + hbb1[tid];
        z1[tid] = fmaxf(acc, 0.0f);
    }
    __syncthreads();
    if (tid < 128) {
        float acc = hb2[tid];
        #pragma unroll 8
        for (int k = 0; k < 256; k++) acc = fmaf(z1[k], hW2[k * 128 + tid], acc);
        acc = (acc - hm2[tid]) * rsqrtf(hv2[tid] + EPS) * hg2[tid] + hbb2[tid];
        z2[tid] = fmaxf(acc, 0.0f);
    }
    __syncthreads();
    if (tid < 64) {
        float acc = hb3[tid];
        #pragma unroll 8
        for (int k = 0; k < 128; k++) acc = fmaf(z2[k], hW3[k * 64 + tid], acc);
        z3[tid] = fmaxf(acc, 0.0f);
    }
    __syncthreads();
    if (tid == 0) {
        float acc = hb4[0];
        #pragma unroll
        for (int k = 0; k < 64; k++) acc = fmaf(z3[k], hW4[k], acc);
        out[g] = acc;
    }
}

// ---------------- launch ----------------
extern "C" void kernel_launch(void* const* d_in, const int* in_sizes, int n_in,
                              void* d_out, int out_size) {
    const float* x      = (const float*)d_in[0];
    const int*   ei     = (const int*)d_in[1];    // [2, E] int32
    const int*   batch  = (const int*)d_in[2];    // [N] int32
    const float* gcn_W0 = (const float*)d_in[3];
    const float* gcn_b0 = (const float*)d_in[4];
    const float* bn_g0  = (const float*)d_in[5];
    const float* bn_b0  = (const float*)d_in[6];
    const float* bn_m0  = (const float*)d_in[7];
    const float* bn_v0  = (const float*)d_in[8];
    const float* gcn_W1 = (const float*)d_in[9];
    const float* gcn_b1 = (const float*)d_in[10];
    const float* bn_g1  = (const float*)d_in[11];
    const float* bn_b1  = (const float*)d_in[12];
    const float* bn_m1  = (const float*)d_in[13];
    const float* bn_v1  = (const float*)d_in[14];
    const float* hW1 = (const float*)d_in[15];
    const float* hb1 = (const float*)d_in[16];
    const float* hg1 = (const float*)d_in[17];
    const float* hbb1= (const float*)d_in[18];
    const float* hm1 = (const float*)d_in[19];
    const float* hv1 = (const float*)d_in[20];
    const float* hW2 = (const float*)d_in[21];
    const float* hb2 = (const float*)d_in[22];
    const float* hg2 = (const float*)d_in[23];
    const float* hbb2= (const float*)d_in[24];
    const float* hm2 = (const float*)d_in[25];
    const float* hv2 = (const float*)d_in[26];
    const float* hW3 = (const float*)d_in[27];
    const float* hb3 = (const float*)d_in[28];
    const float* hW4 = (const float*)d_in[29];
    const float* hb4 = (const float*)d_in[30];
    float* out = (float*)d_out;

    const int* erow = ei;             // source
    const int* ecol = ei + N_EDGES;   // target

    float *p_xw = nullptr, *p_agg = nullptr;
    cudaGetSymbolAddress((void**)&p_xw, g_xw);
    cudaGetSymbolAddress((void**)&p_agg, g_agg);

    const int T = 256;
    int gN    = (N_NODES + T - 1) / T;
    int gE    = (N_EDGES + T - 1) / T;
    int gND4  = (N_NODES * D / 4 + T - 1) / T;
    int gRows = (N_NODES + 63) / 64;
    int gScat = (int)(((long long)N_EDGES * 16 + T - 1) / T);
    int gPool = (N_NODES + POOL_NODES - 1) / POOL_NODES;

    // degree / dinv
    k_deg_init<<<gN, T>>>();
    k_deg_count<<<gE, T>>>(ecol);
    k_dinv<<<gN, T>>>();

    // GCN layer 0
    k_gemm64<<<gRows, T>>>(x, gcn_W0, p_xw);
    k_zero_agg<<<gND4, T>>>();
    k_scatter<<<gScat, T>>>(erow, ecol);
    k_epilogue<<<gND4, T>>>(gcn_b0, bn_g0, bn_b0, bn_m0, bn_v0);

    // GCN layer 1
    k_gemm64<<<gRows, T>>>(p_agg, gcn_W1, p_xw);
    k_zero_agg<<<gND4, T>>>();
    k_scatter<<<gScat, T>>>(erow, ecol);
    k_epilogue<<<gND4, T>>>(gcn_b1, bn_g1, bn_b1, bn_m1, bn_v1);

    // pool
    k_zero_pool<<<(NUM_GRAPHS * D + T - 1) / T, T>>>();
    k_pool<<<gPool, 64>>>(batch);

    // MLP head
    k_mlp<<<NUM_GRAPHS, 256>>>(hW1, hb1, hg1, hbb1, hm1, hv1,
                               hW2, hb2, hg2, hbb2, hm2, hv2,
                               hW3, hb3, hW4, hb4, out);
}

// round 5
// speedup vs baseline: 1.5209x; 1.5209x over previous
#include <cuda_runtime.h>
#include <cuda_bf16.h>

#define N_NODES 50000
#define N_EDGES 800000
#define NUM_GRAPHS 256
#define D 64
#define EPS 1e-5f

#define SCHUNK 196
#define SBLOCKS 256   // 256*196 = 50176 >= 50000

// ---------------- scratch (device globals; no allocation) ----------------
__device__ float g_xw[N_NODES * D];      // dinv[n] * (A @ W)[n]
__device__ float g_agg[N_NODES * D];     // layer output
__device__ float g_deg[N_NODES];         // 1 + in-degree (float)
__device__ float g_dinv[N_NODES];
__device__ int   g_esrc[N_EDGES];        // source ids, grouped by target (CSR)
__device__ int   g_startv[N_NODES];      // CSR row start
__device__ int   g_pos[N_NODES];         // placement cursor -> row end
__device__ int   g_part[SBLOCKS];
__device__ int   g_base[SBLOCKS];
__device__ float g_pooled[NUM_GRAPHS * D];
__device__ float g_cnt[NUM_GRAPHS];

// ---------------- degree ----------------
__global__ void k_deg_init() {
    int i = blockIdx.x * blockDim.x + threadIdx.x;
    if (i < N_NODES) g_deg[i] = 1.0f;  // self-loop
}
__global__ void k_deg_count(const int* __restrict__ col) {
    int e = blockIdx.x * blockDim.x + threadIdx.x;
    if (e < N_EDGES) atomicAdd(&g_deg[col[e]], 1.0f);
}
__global__ void k_dinv() {
    int i = blockIdx.x * blockDim.x + threadIdx.x;
    if (i < N_NODES) g_dinv[i] = rsqrtf(g_deg[i]);
}

// ---------------- prefix scan of in-degree (3 phases) ----------------
__global__ void k_scan_partial() {
    __shared__ int sh[256];
    int b = blockIdx.x, t = threadIdx.x;
    int n = b * SCHUNK + t;
    int v = 0;
    if (t < SCHUNK && n < N_NODES) v = (int)g_deg[n] - 1;
    sh[t] = v;
    __syncthreads();
    for (int off = 128; off > 0; off >>= 1) {
        if (t < off) sh[t] += sh[t + off];
        __syncthreads();
    }
    if (t == 0) g_part[b] = sh[0];
}
__global__ void k_scan_base() {
    __shared__ int sh[256];
    int t = threadIdx.x;
    int v = g_part[t];
    sh[t] = v;
    __syncthreads();
    for (int off = 1; off < 256; off <<= 1) {
        int add = (t >= off) ? sh[t - off] : 0;
        __syncthreads();
        sh[t] += add;
        __syncthreads();
    }
    g_base[t] = sh[t] - v;  // exclusive
}
__global__ void k_scan_chunk() {
    __shared__ int sh[256];
    int b = blockIdx.x, t = threadIdx.x;
    int n = b * SCHUNK + t;
    int v = 0;
    if (t < SCHUNK && n < N_NODES) v = (int)g_deg[n] - 1;
    sh[t] = v;
    __syncthreads();
    for (int off = 1; off < 256; off <<= 1) {
        int add = (t >= off) ? sh[t - off] : 0;
        __syncthreads();
        sh[t] += add;
        __syncthreads();
    }
    if (t < SCHUNK && n < N_NODES) {
        int start = g_base[b] + sh[t] - v;  // exclusive within chunk + base
        g_startv[n] = start;
        g_pos[n] = start;
    }
}
// place edges: group sources by target
__global__ void k_place(const int* __restrict__ row, const int* __restrict__ col) {
    int e = blockIdx.x * blockDim.x + threadIdx.x;
    if (e >= N_EDGES) return;
    int c = col[e];
    int slot = atomicAdd(&g_pos[c], 1);
    g_esrc[slot] = row[e];
}

// ---------------- GEMM: C[n,:] = dinv[n] * (A[n,:] @ W)  (R3 structure) ----------------
__global__ void k_gemm64(const float* __restrict__ A,
                         const float* __restrict__ W,
                         float* __restrict__ C) {
    __shared__ float Ws[64][65];
    __shared__ float As[64][65];
    int row0 = blockIdx.x * 64;
    int tid = threadIdx.x;
    #pragma unroll
    for (int i = tid; i < 4096; i += 256) {
        Ws[i >> 6][i & 63] = W[i];
        int r = i >> 6, c = i & 63;
        As[r][c] = (row0 + r < N_NODES) ? A[(row0 + r) * D + c] : 0.0f;
    }
    __syncthreads();
    #pragma unroll
    for (int t = 0; t < 16; t++) {
        int idx = t * 256 + tid;
        int r = idx >> 6, c = idx & 63;
        float acc = 0.0f;
        #pragma unroll
        for (int k = 0; k < 64; k++) acc = fmaf(As[r][k], Ws[k][c], acc);
        if (row0 + r < N_NODES) C[(row0 + r) * D + c] = acc * g_dinv[row0 + r];
    }
}

// ---------------- gather-aggregate + self-loop + bias + BN + ReLU ----------------
// one warp per target node; lane owns cols 2*lane, 2*lane+1 (float2).
__global__ void k_agg(const float* __restrict__ b,
                      const float* __restrict__ bg,
                      const float* __restrict__ bb,
                      const float* __restrict__ bm,
                      const float* __restrict__ bv) {
    int w = (blockIdx.x * blockDim.x + threadIdx.x) >> 5;  // node
    int lane = threadIdx.x & 31;
    if (w >= N_NODES) return;
    int s0 = g_startv[w];
    int s1 = g_pos[w];          // end (cursor after placement)
    int cb = 2 * lane;

    // self-loop message = xw'[w]  (xw' already has dinv[w] folded in)
    float2 acc = *(const float2*)(g_xw + w * D + cb);
    for (int j = s0; j < s1; j++) {
        int r = __ldg(&g_esrc[j]);  // warp-uniform broadcast
        float2 v = *(const float2*)(g_xw + r * D + cb);
        acc.x += v.x;
        acc.y += v.y;
    }
    float dc = g_dinv[w];
    float2 bj  = *(const float2*)(b  + cb);
    float2 mj  = *(const float2*)(bm + cb);
    float2 vj  = *(const float2*)(bv + cb);
    float2 gj  = *(const float2*)(bg + cb);
    float2 bbj = *(const float2*)(bb + cb);
    float2 o;
    o.x = fmaxf((dc * acc.x + bj.x - mj.x) * rsqrtf(vj.x + EPS) * gj.x + bbj.x, 0.f);
    o.y = fmaxf((dc * acc.y + bj.y - mj.y) * rsqrtf(vj.y + EPS) * gj.y + bbj.y, 0.f);
    *(float2*)(g_agg + w * D + cb) = o;
}

// ---------------- global mean pool: run-length segment reduce (batch sorted) ----------------
__global__ void k_zero_pool() {
    int i = blockIdx.x * blockDim.x + threadIdx.x;
    if (i < NUM_GRAPHS * D) g_pooled[i] = 0.0f;
    if (i < NUM_GRAPHS) g_cnt[i] = 0.0f;
}
#define POOL_NODES 200
__global__ void k_pool(const int* __restrict__ batch) {
    int c = threadIdx.x;  // 64 threads = one column each
    int n0 = blockIdx.x * POOL_NODES;
    int n1 = n0 + POOL_NODES; if (n1 > N_NODES) n1 = N_NODES;
    if (n0 >= N_NODES) return;
    int cur = __ldg(&batch[n0]);
    float acc = 0.f, cnt = 0.f;
    for (int n = n0; n < n1; n++) {
        int bkt = __ldg(&batch[n]);
        if (bkt != cur) {
            atomicAdd(&g_pooled[cur * D + c], acc);
            if (c == 0) atomicAdd(&g_cnt[cur], cnt);
            cur = bkt; acc = 0.f; cnt = 0.f;
        }
        acc += g_agg[n * D + c];
        cnt += 1.f;
    }
    atomicAdd(&g_pooled[cur * D + c], acc);
    if (c == 0) atomicAdd(&g_cnt[cur], cnt);
}

// ---------------- MLP head: one block per graph ----------------
__global__ void k_mlp(const float* __restrict__ hW1, const float* __restrict__ hb1,
                      const float* __restrict__ hg1, const float* __restrict__ hbb1,
                      const float* __restrict__ hm1, const float* __restrict__ hv1,
                      const float* __restrict__ hW2, const float* __restrict__ hb2,
                      const float* __restrict__ hg2, const float* __restrict__ hbb2,
                      const float* __restrict__ hm2, const float* __restrict__ hv2,
                      const float* __restrict__ hW3, const float* __restrict__ hb3,
                      const float* __restrict__ hW4, const float* __restrict__ hb4,
                      float* __restrict__ out) {
    __shared__ float p[64];
    __shared__ float z1[256];
    __shared__ float z2[128];
    __shared__ float z3[64];
    int g = blockIdx.x;
    int tid = threadIdx.x;
    if (tid < 64) {
        float c = fmaxf(g_cnt[g], 1.0f);
        p[tid] = g_pooled[g * D + tid] / c;
    }
    __syncthreads();
    {
        float acc = hb1[tid];
        #pragma unroll
        for (int k = 0; k < 64; k++) acc = fmaf(p[k], hW1[k * 256 + tid], acc);
        acc = (acc - hm1[tid]) * rsqrtf(hv1[tid] + EPS) * hg1[tid] + hbb1[tid];
        z1[tid] = fmaxf(acc, 0.0f);
    }
    __syncthreads();
    if (tid < 128) {
        float acc = hb2[tid];
        #pragma unroll 8
        for (int k = 0; k < 256; k++) acc = fmaf(z1[k], hW2[k * 128 + tid], acc);
        acc = (acc - hm2[tid]) * rsqrtf(hv2[tid] + EPS) * hg2[tid] + hbb2[tid];
        z2[tid] = fmaxf(acc, 0.0f);
    }
    __syncthreads();
    if (tid < 64) {
        float acc = hb3[tid];
        #pragma unroll 8
        for (int k = 0; k < 128; k++) acc = fmaf(z2[k], hW3[k * 64 + tid], acc);
        z3[tid] = fmaxf(acc, 0.0f);
    }
    __syncthreads();
    if (tid == 0) {
        float acc = hb4[0];
        #pragma unroll
        for (int k = 0; k < 64; k++) acc = fmaf(z3[k], hW4[k], acc);
        out[g] = acc;
    }
}

// ---------------- launch ----------------
extern "C" void kernel_launch(void* const* d_in, const int* in_sizes, int n_in,
                              void* d_out, int out_size) {
    const float* x      = (const float*)d_in[0];
    const int*   ei     = (const int*)d_in[1];    // [2, E] int32
    const int*   batch  = (const int*)d_in[2];    // [N] int32
    const float* gcn_W0 = (const float*)d_in[3];
    const float* gcn_b0 = (const float*)d_in[4];
    const float* bn_g0  = (const float*)d_in[5];
    const float* bn_b0  = (const float*)d_in[6];
    const float* bn_m0  = (const float*)d_in[7];
    const float* bn_v0  = (const float*)d_in[8];
    const float* gcn_W1 = (const float*)d_in[9];
    const float* gcn_b1 = (const float*)d_in[10];
    const float* bn_g1  = (const float*)d_in[11];
    const float* bn_b1  = (const float*)d_in[12];
    const float* bn_m1  = (const float*)d_in[13];
    const float* bn_v1  = (const float*)d_in[14];
    const float* hW1 = (const float*)d_in[15];
    const float* hb1 = (const float*)d_in[16];
    const float* hg1 = (const float*)d_in[17];
    const float* hbb1= (const float*)d_in[18];
    const float* hm1 = (const float*)d_in[19];
    const float* hv1 = (const float*)d_in[20];
    const float* hW2 = (const float*)d_in[21];
    const float* hb2 = (const float*)d_in[22];
    const float* hg2 = (const float*)d_in[23];
    const float* hbb2= (const float*)d_in[24];
    const float* hm2 = (const float*)d_in[25];
    const float* hv2 = (const float*)d_in[26];
    const float* hW3 = (const float*)d_in[27];
    const float* hb3 = (const float*)d_in[28];
    const float* hW4 = (const float*)d_in[29];
    const float* hb4 = (const float*)d_in[30];
    float* out = (float*)d_out;

    const int* erow = ei;             // source
    const int* ecol = ei + N_EDGES;   // target

    float *p_xw = nullptr, *p_agg = nullptr;
    cudaGetSymbolAddress((void**)&p_xw, g_xw);
    cudaGetSymbolAddress((void**)&p_agg, g_agg);

    const int T = 256;
    int gN    = (N_NODES + T - 1) / T;
    int gE    = (N_EDGES + T - 1) / T;
    int gRows = (N_NODES + 63) / 64;
    int gAgg  = (int)(((long long)N_NODES * 32 + T - 1) / T);
    int gPool = (N_NODES + POOL_NODES - 1) / POOL_NODES;

    // degree / dinv / CSR build (reused by both layers)
    k_deg_init<<<gN, T>>>();
    k_deg_count<<<gE, T>>>(ecol);
    k_dinv<<<gN, T>>>();
    k_scan_partial<<<SBLOCKS, 256>>>();
    k_scan_base<<<1, 256>>>();
    k_scan_chunk<<<SBLOCKS, 256>>>();
    k_place<<<gE, T>>>(erow, ecol);

    // GCN layer 0
    k_gemm64<<<gRows, T>>>(x, gcn_W0, p_xw);
    k_agg<<<gAgg, T>>>(gcn_b0, bn_g0, bn_b0, bn_m0, bn_v0);

    // GCN layer 1
    k_gemm64<<<gRows, T>>>(p_agg, gcn_W1, p_xw);
    k_agg<<<gAgg, T>>>(gcn_b1, bn_g1, bn_b1, bn_m1, bn_v1);

    // pool
    k_zero_pool<<<(NUM_GRAPHS * D + T - 1) / T, T>>>();
    k_pool<<<gPool, 64>>>(batch);

    // MLP head
    k_mlp<<<NUM_GRAPHS, 256>>>(hW1, hb1, hg1, hbb1, hm1, hv1,
                               hW2, hb2, hg2, hbb2, hm2, hv2,
                               hW3, hb3, hW4, hb4, out);
}

// round 6
// speedup vs baseline: 1.8452x; 1.2132x over previous
#include <cuda_runtime.h>
#include <cuda_bf16.h>

#define N_NODES 50000
#define N_EDGES 800000
#define NUM_GRAPHS 256
#define D 64
#define EPS 1e-5f

#define SCHUNK 196
#define SBLOCKS 256   // 256*196 = 50176 >= 50000

// ---------------- scratch (device globals; no allocation) ----------------
__device__ float g_xw[N_NODES * D];      // dinv[n] * (A @ W)[n]
__device__ float g_agg[N_NODES * D];     // layer output
__device__ float g_deg[N_NODES];         // 1 + in-degree (float)
__device__ float g_dinv[N_NODES];
__device__ int   g_esrc[N_EDGES];        // source ids, grouped by target (CSR)
__device__ int   g_startv[N_NODES];      // CSR row start
__device__ int   g_pos[N_NODES];         // placement cursor -> row end
__device__ int   g_part[SBLOCKS];
__device__ int   g_base[SBLOCKS];
__device__ float g_pooled[NUM_GRAPHS * D];
__device__ float g_cnt[NUM_GRAPHS];

// ---------------- degree ----------------
__global__ void k_deg_init() {
    int i = blockIdx.x * blockDim.x + threadIdx.x;
    if (i < N_NODES) g_deg[i] = 1.0f;  // self-loop
}
__global__ void k_deg_count(const int* __restrict__ col) {
    int e = blockIdx.x * blockDim.x + threadIdx.x;
    if (e < N_EDGES) atomicAdd(&g_deg[col[e]], 1.0f);
}
__global__ void k_dinv() {
    int i = blockIdx.x * blockDim.x + threadIdx.x;
    if (i < N_NODES) g_dinv[i] = rsqrtf(g_deg[i]);
}

// ---------------- prefix scan of in-degree (3 phases) ----------------
__global__ void k_scan_partial() {
    __shared__ int sh[256];
    int b = blockIdx.x, t = threadIdx.x;
    int n = b * SCHUNK + t;
    int v = 0;
    if (t < SCHUNK && n < N_NODES) v = (int)g_deg[n] - 1;
    sh[t] = v;
    __syncthreads();
    for (int off = 128; off > 0; off >>= 1) {
        if (t < off) sh[t] += sh[t + off];
        __syncthreads();
    }
    if (t == 0) g_part[b] = sh[0];
}
__global__ void k_scan_base() {
    __shared__ int sh[256];
    int t = threadIdx.x;
    int v = g_part[t];
    sh[t] = v;
    __syncthreads();
    for (int off = 1; off < 256; off <<= 1) {
        int add = (t >= off) ? sh[t - off] : 0;
        __syncthreads();
        sh[t] += add;
        __syncthreads();
    }
    g_base[t] = sh[t] - v;  // exclusive
}
__global__ void k_scan_chunk() {
    __shared__ int sh[256];
    int b = blockIdx.x, t = threadIdx.x;
    int n = b * SCHUNK + t;
    int v = 0;
    if (t < SCHUNK && n < N_NODES) v = (int)g_deg[n] - 1;
    sh[t] = v;
    __syncthreads();
    for (int off = 1; off < 256; off <<= 1) {
        int add = (t >= off) ? sh[t - off] : 0;
        __syncthreads();
        sh[t] += add;
        __syncthreads();
    }
    if (t < SCHUNK && n < N_NODES) {
        int start = g_base[b] + sh[t] - v;
        g_startv[n] = start;
        g_pos[n] = start;
    }
}
__global__ void k_place(const int* __restrict__ row, const int* __restrict__ col) {
    int e = blockIdx.x * blockDim.x + threadIdx.x;
    if (e >= N_EDGES) return;
    int c = col[e];
    int slot = atomicAdd(&g_pos[c], 1);
    g_esrc[slot] = row[e];
}

// ---------------- GEMM: C[n,:] = dinv[n] * (A[n,:] @ W) ----------------
// 4x4 register tiling: 256 threads = 16x16 grid, each thread does 4 rows x 4 cols.
// A: padded smem, broadcast scalar reads. W: float4 rows, LDS.128 conflict-free.
__global__ void k_gemm64(const float* __restrict__ A,
                         const float* __restrict__ W,
                         float* __restrict__ C) {
    __shared__ float  As[64][65];
    __shared__ float4 Ws4[64][16];
    int tid = threadIdx.x;
    int row0 = blockIdx.x * 64;

    #pragma unroll
    for (int i = tid; i < 1024; i += 256)
        Ws4[i >> 4][i & 15] = ((const float4*)W)[i];
    #pragma unroll
    for (int i = tid; i < 4096; i += 256) {
        int r = i >> 6, c = i & 63;
        As[r][c] = (row0 + r < N_NODES) ? A[(row0 + r) * D + c] : 0.0f;
    }
    __syncthreads();

    int tx = tid & 15;   // col group: cols tx*4 .. +3
    int ty = tid >> 4;   // row group: rows ty*4 .. +3

    float4 acc0 = {0,0,0,0}, acc1 = {0,0,0,0}, acc2 = {0,0,0,0}, acc3 = {0,0,0,0};

    #pragma unroll
    for (int k = 0; k < 64; k++) {
        float4 w = Ws4[k][tx];
        float a0 = As[ty * 4 + 0][k];
        float a1 = As[ty * 4 + 1][k];
        float a2 = As[ty * 4 + 2][k];
        float a3 = As[ty * 4 + 3][k];
        acc0.x = fmaf(a0, w.x, acc0.x); acc0.y = fmaf(a0, w.y, acc0.y);
        acc0.z = fmaf(a0, w.z, acc0.z); acc0.w = fmaf(a0, w.w, acc0.w);
        acc1.x = fmaf(a1, w.x, acc1.x); acc1.y = fmaf(a1, w.y, acc1.y);
        acc1.z = fmaf(a1, w.z, acc1.z); acc1.w = fmaf(a1, w.w, acc1.w);
        acc2.x = fmaf(a2, w.x, acc2.x); acc2.y = fmaf(a2, w.y, acc2.y);
        acc2.z = fmaf(a2, w.z, acc2.z); acc2.w = fmaf(a2, w.w, acc2.w);
        acc3.x = fmaf(a3, w.x, acc3.x); acc3.y = fmaf(a3, w.y, acc3.y);
        acc3.z = fmaf(a3, w.z, acc3.z); acc3.w = fmaf(a3, w.w, acc3.w);
    }

    #pragma unroll
    for (int i = 0; i < 4; i++) {
        int r = row0 + ty * 4 + i;
        if (r < N_NODES) {
            float d = g_dinv[r];
            float4 v = (i == 0) ? acc0 : (i == 1) ? acc1 : (i == 2) ? acc2 : acc3;
            v.x *= d; v.y *= d; v.z *= d; v.w *= d;
            *((float4*)(C + r * D) + tx) = v;
        }
    }
}

// ---------------- gather-aggregate + self-loop + bias + BN + ReLU ----------------
// one warp per target node; lane owns cols 2*lane, 2*lane+1 (float2).
__global__ void k_agg(const float* __restrict__ b,
                      const float* __restrict__ bg,
                      const float* __restrict__ bb,
                      const float* __restrict__ bm,
                      const float* __restrict__ bv) {
    int w = (blockIdx.x * blockDim.x + threadIdx.x) >> 5;  // node
    int lane = threadIdx.x & 31;
    if (w >= N_NODES) return;
    int s0 = g_startv[w];
    int s1 = g_pos[w];
    int cb = 2 * lane;

    float2 acc = *(const float2*)(g_xw + w * D + cb);  // self-loop
    for (int j = s0; j < s1; j++) {
        int r = __ldg(&g_esrc[j]);
        float2 v = *(const float2*)(g_xw + r * D + cb);
        acc.x += v.x;
        acc.y += v.y;
    }
    float dc = g_dinv[w];
    float2 bj  = *(const float2*)(b  + cb);
    float2 mj  = *(const float2*)(bm + cb);
    float2 vj  = *(const float2*)(bv + cb);
    float2 gj  = *(const float2*)(bg + cb);
    float2 bbj = *(const float2*)(bb + cb);
    float2 o;
    o.x = fmaxf((dc * acc.x + bj.x - mj.x) * rsqrtf(vj.x + EPS) * gj.x + bbj.x, 0.f);
    o.y = fmaxf((dc * acc.y + bj.y - mj.y) * rsqrtf(vj.y + EPS) * gj.y + bbj.y, 0.f);
    *(float2*)(g_agg + w * D + cb) = o;
}

// ---------------- global mean pool ----------------
__global__ void k_zero_pool() {
    int i = blockIdx.x * blockDim.x + threadIdx.x;
    if (i < NUM_GRAPHS * D) g_pooled[i] = 0.0f;
    if (i < NUM_GRAPHS) g_cnt[i] = 0.0f;
}
#define POOL_NODES 200
__global__ void k_pool(const int* __restrict__ batch) {
    int c = threadIdx.x;
    int n0 = blockIdx.x * POOL_NODES;
    int n1 = n0 + POOL_NODES; if (n1 > N_NODES) n1 = N_NODES;
    if (n0 >= N_NODES) return;
    int cur = __ldg(&batch[n0]);
    float acc = 0.f, cnt = 0.f;
    for (int n = n0; n < n1; n++) {
        int bkt = __ldg(&batch[n]);
        if (bkt != cur) {
            atomicAdd(&g_pooled[cur * D + c], acc);
            if (c == 0) atomicAdd(&g_cnt[cur], cnt);
            cur = bkt; acc = 0.f; cnt = 0.f;
        }
        acc += g_agg[n * D + c];
        cnt += 1.f;
    }
    atomicAdd(&g_pooled[cur * D + c], acc);
    if (c == 0) atomicAdd(&g_cnt[cur], cnt);
}

// ---------------- MLP head ----------------
__global__ void k_mlp(const float* __restrict__ hW1, const float* __restrict__ hb1,
                      const float* __restrict__ hg1, const float* __restrict__ hbb1,
                      const float* __restrict__ hm1, const float* __restrict__ hv1,
                      const float* __restrict__ hW2, const float* __restrict__ hb2,
                      const float* __restrict__ hg2, const float* __restrict__ hbb2,
                      const float* __restrict__ hm2, const float* __restrict__ hv2,
                      const float* __restrict__ hW3, const float* __restrict__ hb3,
                      const float* __restrict__ hW4, const float* __restrict__ hb4,
                      float* __restrict__ out) {
    __shared__ float p[64];
    __shared__ float z1[256];
    __shared__ float z2[128];
    __shared__ float z3[64];
    int g = blockIdx.x;
    int tid = threadIdx.x;
    if (tid < 64) {
        float c = fmaxf(g_cnt[g], 1.0f);
        p[tid] = g_pooled[g * D + tid] / c;
    }
    __syncthreads();
    {
        float acc = hb1[tid];
        #pragma unroll
        for (int k = 0; k < 64; k++) acc = fmaf(p[k], hW1[k * 256 + tid], acc);
        acc = (acc - hm1[tid]) * rsqrtf(hv1[tid] + EPS) * hg1[tid] + hbb1[tid];
        z1[tid] = fmaxf(acc, 0.0f);
    }
    __syncthreads();
    if (tid < 128) {
        float acc = hb2[tid];
        #pragma unroll 8
        for (int k = 0; k < 256; k++) acc = fmaf(z1[k], hW2[k * 128 + tid], acc);
        acc = (acc - hm2[tid]) * rsqrtf(hv2[tid] + EPS) * hg2[tid] + hbb2[tid];
        z2[tid] = fmaxf(acc, 0.0f);
    }
    __syncthreads();
    if (tid < 64) {
        float acc = hb3[tid];
        #pragma unroll 8
        for (int k = 0; k < 128; k++) acc = fmaf(z2[k], hW3[k * 64 + tid], acc);
        z3[tid] = fmaxf(acc, 0.0f);
    }
    __syncthreads();
    if (tid == 0) {
        float acc = hb4[0];
        #pragma unroll
        for (int k = 0; k < 64; k++) acc = fmaf(z3[k], hW4[k], acc);
        out[g] = acc;
    }
}

// ---------------- launch ----------------
extern "C" void kernel_launch(void* const* d_in, const int* in_sizes, int n_in,
                              void* d_out, int out_size) {
    const float* x      = (const float*)d_in[0];
    const int*   ei     = (const int*)d_in[1];
    const int*   batch  = (const int*)d_in[2];
    const float* gcn_W0 = (const float*)d_in[3];
    const float* gcn_b0 = (const float*)d_in[4];
    const float* bn_g0  = (const float*)d_in[5];
    const float* bn_b0  = (const float*)d_in[6];
    const float* bn_m0  = (const float*)d_in[7];
    const float* bn_v0  = (const float*)d_in[8];
    const float* gcn_W1 = (const float*)d_in[9];
    const float* gcn_b1 = (const float*)d_in[10];
    const float* bn_g1  = (const float*)d_in[11];
    const float* bn_b1  = (const float*)d_in[12];
    const float* bn_m1  = (const float*)d_in[13];
    const float* bn_v1  = (const float*)d_in[14];
    const float* hW1 = (const float*)d_in[15];
    const float* hb1 = (const float*)d_in[16];
    const float* hg1 = (const float*)d_in[17];
    const float* hbb1= (const float*)d_in[18];
    const float* hm1 = (const float*)d_in[19];
    const float* hv1 = (const float*)d_in[20];
    const float* hW2 = (const float*)d_in[21];
    const float* hb2 = (const float*)d_in[22];
    const float* hg2 = (const float*)d_in[23];
    const float* hbb2= (const float*)d_in[24];
    const float* hm2 = (const float*)d_in[25];
    const float* hv2 = (const float*)d_in[26];
    const float* hW3 = (const float*)d_in[27];
    const float* hb3 = (const float*)d_in[28];
    const float* hW4 = (const float*)d_in[29];
    const float* hb4 = (const float*)d_in[30];
    float* out = (float*)d_out;

    const int* erow = ei;
    const int* ecol = ei + N_EDGES;

    float *p_xw = nullptr, *p_agg = nullptr;
    cudaGetSymbolAddress((void**)&p_xw, g_xw);
    cudaGetSymbolAddress((void**)&p_agg, g_agg);

    const int T = 256;
    int gN    = (N_NODES + T - 1) / T;
    int gE    = (N_EDGES + T - 1) / T;
    int gRows = (N_NODES + 63) / 64;
    int gAgg  = (int)(((long long)N_NODES * 32 + T - 1) / T);
    int gPool = (N_NODES + POOL_NODES - 1) / POOL_NODES;

    // degree / dinv / CSR build
    k_deg_init<<<gN, T>>>();
    k_deg_count<<<gE, T>>>(ecol);
    k_dinv<<<gN, T>>>();
    k_scan_partial<<<SBLOCKS, 256>>>();
    k_scan_base<<<1, 256>>>();
    k_scan_chunk<<<SBLOCKS, 256>>>();
    k_place<<<gE, T>>>(erow, ecol);

    // GCN layer 0
    k_gemm64<<<gRows, T>>>(x, gcn_W0, p_xw);
    k_agg<<<gAgg, T>>>(gcn_b0, bn_g0, bn_b0, bn_m0, bn_v0);

    // GCN layer 1
    k_gemm64<<<gRows, T>>>(p_agg, gcn_W1, p_xw);
    k_agg<<<gAgg, T>>>(gcn_b1, bn_g1, bn_b1, bn_m1, bn_v1);

    // pool
    k_zero_pool<<<(NUM_GRAPHS * D + T - 1) / T, T>>>();
    k_pool<<<gPool, 64>>>(batch);

    // MLP head
    k_mlp<<<NUM_GRAPHS, 256>>>(hW1, hb1, hg1, hbb1, hm1, hv1,
                               hW2, hb2, hg2, hbb2, hm2, hv2,
                               hW3, hb3, hW4, hb4, out);
}

// round 7
// speedup vs baseline: 1.8737x; 1.0154x over previous
#include <cuda_runtime.h>
#include <cuda_bf16.h>

#define N_NODES 50000
#define N_EDGES 800000
#define NUM_GRAPHS 256
#define D 64
#define EPS 1e-5f

#define SCHUNK 196
#define SBLOCKS 256   // 256*196 = 50176 >= 50000

// ---------------- scratch (device globals; no allocation) ----------------
__device__ float g_xw[N_NODES * D];      // dinv[n] * (A @ W)[n]
__device__ float g_agg[N_NODES * D];     // layer output
__device__ float g_deg[N_NODES];         // 1 + in-degree (float)
__device__ float g_dinv[N_NODES];
__device__ int   g_esrc[N_EDGES];        // source ids, grouped by target (CSR)
__device__ int   g_startv[N_NODES];      // CSR row start
__device__ int   g_pos[N_NODES];         // placement cursor -> row end
__device__ int   g_part[SBLOCKS];
__device__ float g_pooled[NUM_GRAPHS * D];
__device__ float g_cnt[NUM_GRAPHS];

// ---------------- init: deg=1 (self-loop) + zero pool ----------------
__global__ void k_init() {
    int i = blockIdx.x * blockDim.x + threadIdx.x;
    if (i < N_NODES) g_deg[i] = 1.0f;
    if (i < NUM_GRAPHS * D) g_pooled[i] = 0.0f;
    if (i < NUM_GRAPHS) g_cnt[i] = 0.0f;
}

__global__ void k_deg_count(const int* __restrict__ col) {
    int e = blockIdx.x * blockDim.x + threadIdx.x;
    if (e < N_EDGES) atomicAdd(&g_deg[col[e]], 1.0f);
}

// ---------------- scan phase 1: per-chunk totals (+ dinv fused) ----------------
__global__ void k_scan_partial() {
    __shared__ int sh[256];
    int b = blockIdx.x, t = threadIdx.x;
    int n = b * SCHUNK + t;
    int v = 0;
    if (t < SCHUNK && n < N_NODES) {
        float d = g_deg[n];
        g_dinv[n] = rsqrtf(d);
        v = (int)d - 1;
    }
    sh[t] = v;
    __syncthreads();
    for (int off = 128; off > 0; off >>= 1) {
        if (t < off) sh[t] += sh[t + off];
        __syncthreads();
    }
    if (t == 0) g_part[b] = sh[0];
}

// ---------------- scan phase 2: chunk scan with inline base reduction ----------------
__global__ void k_scan_chunk() {
    __shared__ int sh[256];
    __shared__ int bs[256];
    int b = blockIdx.x, t = threadIdx.x;
    bs[t] = (t < b) ? g_part[t] : 0;
    int n = b * SCHUNK + t;
    int v = 0;
    if (t < SCHUNK && n < N_NODES) v = (int)g_deg[n] - 1;
    sh[t] = v;
    __syncthreads();
    for (int off = 128; off > 0; off >>= 1) {
        if (t < off) bs[t] += bs[t + off];
        __syncthreads();
    }
    for (int off = 1; off < 256; off <<= 1) {
        int add = (t >= off) ? sh[t - off] : 0;
        __syncthreads();
        sh[t] += add;
        __syncthreads();
    }
    if (t < SCHUNK && n < N_NODES) {
        int start = bs[0] + sh[t] - v;
        g_startv[n] = start;
        g_pos[n] = start;
    }
}

__global__ void k_place(const int* __restrict__ row, const int* __restrict__ col) {
    int e = blockIdx.x * blockDim.x + threadIdx.x;
    if (e >= N_EDGES) return;
    int c = col[e];
    int slot = atomicAdd(&g_pos[c], 1);
    g_esrc[slot] = row[e];
}

// ---------------- GEMM: C[n,:] = dinv[n] * (A[n,:] @ W)  (4x4 register tile) ----------------
__global__ void k_gemm64(const float* __restrict__ A,
                         const float* __restrict__ W,
                         float* __restrict__ C,
                         int use_dinv) {
    __shared__ float  As[64][65];
    __shared__ float4 Ws4[64][16];
    int tid = threadIdx.x;
    int row0 = blockIdx.x * 64;

    #pragma unroll
    for (int i = tid; i < 1024; i += 256)
        Ws4[i >> 4][i & 15] = ((const float4*)W)[i];
    #pragma unroll
    for (int i = tid; i < 4096; i += 256) {
        int r = i >> 6, c = i & 63;
        As[r][c] = (row0 + r < N_NODES) ? A[(row0 + r) * D + c] : 0.0f;
    }
    __syncthreads();

    int tx = tid & 15;
    int ty = tid >> 4;

    float4 acc0 = {0,0,0,0}, acc1 = {0,0,0,0}, acc2 = {0,0,0,0}, acc3 = {0,0,0,0};

    #pragma unroll
    for (int k = 0; k < 64; k++) {
        float4 w = Ws4[k][tx];
        float a0 = As[ty * 4 + 0][k];
        float a1 = As[ty * 4 + 1][k];
        float a2 = As[ty * 4 + 2][k];
        float a3 = As[ty * 4 + 3][k];
        acc0.x = fmaf(a0, w.x, acc0.x); acc0.y = fmaf(a0, w.y, acc0.y);
        acc0.z = fmaf(a0, w.z, acc0.z); acc0.w = fmaf(a0, w.w, acc0.w);
        acc1.x = fmaf(a1, w.x, acc1.x); acc1.y = fmaf(a1, w.y, acc1.y);
        acc1.z = fmaf(a1, w.z, acc1.z); acc1.w = fmaf(a1, w.w, acc1.w);
        acc2.x = fmaf(a2, w.x, acc2.x); acc2.y = fmaf(a2, w.y, acc2.y);
        acc2.z = fmaf(a2, w.z, acc2.z); acc2.w = fmaf(a2, w.w, acc2.w);
        acc3.x = fmaf(a3, w.x, acc3.x); acc3.y = fmaf(a3, w.y, acc3.y);
        acc3.z = fmaf(a3, w.z, acc3.z); acc3.w = fmaf(a3, w.w, acc3.w);
    }

    #pragma unroll
    for (int i = 0; i < 4; i++) {
        int r = row0 + ty * 4 + i;
        if (r < N_NODES) {
            float d = use_dinv ? g_dinv[r] : 1.0f;
            float4 v = (i == 0) ? acc0 : (i == 1) ? acc1 : (i == 2) ? acc2 : acc3;
            v.x *= d; v.y *= d; v.z *= d; v.w *= d;
            *((float4*)(C + r * D) + tx) = v;
        }
    }
}

// ---------------- gather-aggregate + self-loop + bias + BN + ReLU ----------------
__global__ void k_agg(const float* __restrict__ b,
                      const float* __restrict__ bg,
                      const float* __restrict__ bb,
                      const float* __restrict__ bm,
                      const float* __restrict__ bv) {
    int w = (blockIdx.x * blockDim.x + threadIdx.x) >> 5;
    int lane = threadIdx.x & 31;
    if (w >= N_NODES) return;
    int s0 = g_startv[w];
    int s1 = g_pos[w];
    int cb = 2 * lane;

    float2 acc = *(const float2*)(g_xw + w * D + cb);  // self-loop
    for (int j = s0; j < s1; j++) {
        int r = __ldg(&g_esrc[j]);
        float2 v = *(const float2*)(g_xw + r * D + cb);
        acc.x += v.x;
        acc.y += v.y;
    }
    float dc = g_dinv[w];
    float2 bj  = *(const float2*)(b  + cb);
    float2 mj  = *(const float2*)(bm + cb);
    float2 vj  = *(const float2*)(bv + cb);
    float2 gj  = *(const float2*)(bg + cb);
    float2 bbj = *(const float2*)(bb + cb);
    float2 o;
    o.x = fmaxf((dc * acc.x + bj.x - mj.x) * rsqrtf(vj.x + EPS) * gj.x + bbj.x, 0.f);
    o.y = fmaxf((dc * acc.y + bj.y - mj.y) * rsqrtf(vj.y + EPS) * gj.y + bbj.y, 0.f);
    *(float2*)(g_agg + w * D + cb) = o;
}

// ---------------- global mean pool: run-length segment reduce ----------------
#define POOL_NODES 200
__global__ void k_pool(const int* __restrict__ batch) {
    int c = threadIdx.x;
    int n0 = blockIdx.x * POOL_NODES;
    int n1 = n0 + POOL_NODES; if (n1 > N_NODES) n1 = N_NODES;
    if (n0 >= N_NODES) return;
    int cur = __ldg(&batch[n0]);
    float acc = 0.f, cnt = 0.f;
    for (int n = n0; n < n1; n++) {
        int bkt = __ldg(&batch[n]);
        if (bkt != cur) {
            atomicAdd(&g_pooled[cur * D + c], acc);
            if (c == 0) atomicAdd(&g_cnt[cur], cnt);
            cur = bkt; acc = 0.f; cnt = 0.f;
        }
        acc += g_agg[n * D + c];
        cnt += 1.f;
    }
    atomicAdd(&g_pooled[cur * D + c], acc);
    if (c == 0) atomicAdd(&g_cnt[cur], cnt);
}

// ---------------- MLP head ----------------
__global__ void k_mlp(const float* __restrict__ hW1, const float* __restrict__ hb1,
                      const float* __restrict__ hg1, const float* __restrict__ hbb1,
                      const float* __restrict__ hm1, const float* __restrict__ hv1,
                      const float* __restrict__ hW2, const float* __restrict__ hb2,
                      const float* __restrict__ hg2, const float* __restrict__ hbb2,
                      const float* __restrict__ hm2, const float* __restrict__ hv2,
                      const float* __restrict__ hW3, const float* __restrict__ hb3,
                      const float* __restrict__ hW4, const float* __restrict__ hb4,
                      float* __restrict__ out) {
    __shared__ float p[64];
    __shared__ float z1[256];
    __shared__ float z2[128];
    __shared__ float z3[64];
    int g = blockIdx.x;
    int tid = threadIdx.x;
    if (tid < 64) {
        float c = fmaxf(g_cnt[g], 1.0f);
        p[tid] = g_pooled[g * D + tid] / c;
    }
    __syncthreads();
    {
        float acc = hb1[tid];
        #pragma unroll
        for (int k = 0; k < 64; k++) acc = fmaf(p[k], hW1[k * 256 + tid], acc);
        acc = (acc - hm1[tid]) * rsqrtf(hv1[tid] + EPS) * hg1[tid] + hbb1[tid];
        z1[tid] = fmaxf(acc, 0.0f);
    }
    __syncthreads();
    if (tid < 128) {
        float acc = hb2[tid];
        #pragma unroll 8
        for (int k = 0; k < 256; k++) acc = fmaf(z1[k], hW2[k * 128 + tid], acc);
        acc = (acc - hm2[tid]) * rsqrtf(hv2[tid] + EPS) * hg2[tid] + hbb2[tid];
        z2[tid] = fmaxf(acc, 0.0f);
    }
    __syncthreads();
    if (tid < 64) {
        float acc = hb3[tid];
        #pragma unroll 8
        for (int k = 0; k < 128; k++) acc = fmaf(z2[k], hW3[k * 64 + tid], acc);
        z3[tid] = fmaxf(acc, 0.0f);
    }
    __syncthreads();
    if (tid == 0) {
        float acc = hb4[0];
        #pragma unroll
        for (int k = 0; k < 64; k++) acc = fmaf(z3[k], hW4[k], acc);
        out[g] = acc;
    }
}

// ---------------- launch ----------------
extern "C" void kernel_launch(void* const* d_in, const int* in_sizes, int n_in,
                              void* d_out, int out_size) {
    const float* x      = (const float*)d_in[0];
    const int*   ei     = (const int*)d_in[1];
    const int*   batch  = (const int*)d_in[2];
    const float* gcn_W0 = (const float*)d_in[3];
    const float* gcn_b0 = (const float*)d_in[4];
    const float* bn_g0  = (const float*)d_in[5];
    const float* bn_b0  = (const float*)d_in[6];
    const float* bn_m0  = (const float*)d_in[7];
    const float* bn_v0  = (const float*)d_in[8];
    const float* gcn_W1 = (const float*)d_in[9];
    const float* gcn_b1 = (const float*)d_in[10];
    const float* bn_g1  = (const float*)d_in[11];
    const float* bn_b1  = (const float*)d_in[12];
    const float* bn_m1  = (const float*)d_in[13];
    const float* bn_v1  = (const float*)d_in[14];
    const float* hW1 = (const float*)d_in[15];
    const float* hb1 = (const float*)d_in[16];
    const float* hg1 = (const float*)d_in[17];
    const float* hbb1= (const float*)d_in[18];
    const float* hm1 = (const float*)d_in[19];
    const float* hv1 = (const float*)d_in[20];
    const float* hW2 = (const float*)d_in[21];
    const float* hb2 = (const float*)d_in[22];
    const float* hg2 = (const float*)d_in[23];
    const float* hbb2= (const float*)d_in[24];
    const float* hm2 = (const float*)d_in[25];
    const float* hv2 = (const float*)d_in[26];
    const float* hW3 = (const float*)d_in[27];
    const float* hb3 = (const float*)d_in[28];
    const float* hW4 = (const float*)d_in[29];
    const float* hb4 = (const float*)d_in[30];
    float* out = (float*)d_out;

    const int* erow = ei;
    const int* ecol = ei + N_EDGES;

    float *p_xw = nullptr, *p_agg = nullptr;
    cudaGetSymbolAddress((void**)&p_xw, g_xw);
    cudaGetSymbolAddress((void**)&p_agg, g_agg);

    // Side stream + events for fork/join inside graph capture (host-side
    // resources, created once; no device memory involved).
    static cudaStream_t s_side = nullptr;
    static cudaEvent_t ev_fork = nullptr, ev_join = nullptr;
    if (s_side == nullptr) {
        cudaStreamCreateWithFlags(&s_side, cudaStreamNonBlocking);
        cudaEventCreateWithFlags(&ev_fork, cudaEventDisableTiming);
        cudaEventCreateWithFlags(&ev_join, cudaEventDisableTiming);
    }

    const int T = 256;
    int gN    = (N_NODES + T - 1) / T;
    int gE    = (N_EDGES + T - 1) / T;
    int gRows = (N_NODES + 63) / 64;
    int gAgg  = (int)(((long long)N_NODES * 32 + T - 1) / T);
    int gPool = (N_NODES + POOL_NODES - 1) / POOL_NODES;

    // ---- fork: CSR build on side stream, gemm0 on main stream ----
    cudaEventRecord(ev_fork, 0);
    cudaStreamWaitEvent(s_side, ev_fork, 0);

    // side branch: degrees, scan, placement (depends only on edge_index)
    k_init<<<gN, T, 0, s_side>>>();
    k_deg_count<<<gE, T, 0, s_side>>>(ecol);
    k_scan_partial<<<SBLOCKS, 256, 0, s_side>>>();
    k_scan_chunk<<<SBLOCKS, 256, 0, s_side>>>();
    k_place<<<gE, T, 0, s_side>>>(erow, ecol);
    cudaEventRecord(ev_join, s_side);

    // main branch: gemm0 without dinv scaling yet? No — dinv is produced by the
    // side branch. Instead: gemm0 computes raw A@W (use_dinv=0 would break the
    // factored algorithm). Solution: gemm0 runs concurrently but must apply
    // dinv. So gemm0 waits only if it uses dinv. We keep dinv in gemm -> gemm0
    // must run AFTER scan_partial. Simpler: gemm0 computes raw product into
    // g_xw (use_dinv=0), and k_agg applies dinv[r] per gathered row? That adds
    // a per-edge gather. Instead: scale during agg via dinv[w] only is wrong.
    // Resolution: run gemm0 concurrently WITHOUT dinv, then a tiny fused scale
    // pass is needed — too complex. Pragmatic choice: gemm0 on main stream
    // joins after ev_join, losing gemm0 overlap but keeping CSR fusion wins;
    // gemm0 still overlaps nothing. To regain overlap, we instead overlap the
    // CSR tail (scan/place) with gemm0 by recording a mid-event after
    // k_scan_partial (dinv ready there).
    // (ev_join above covers full CSR; ev_mid covers dinv readiness.)
    static cudaEvent_t ev_mid = nullptr;
    if (ev_mid == nullptr) cudaEventCreateWithFlags(&ev_mid, cudaEventDisableTiming);
    // Re-record events in proper order: ev_mid after scan_partial requires
    // inserting it in the side-stream sequence; easiest is to re-issue:
    // (we already enqueued; instead we enqueue gemm0 waiting on ev_join is
    // safe but loses overlap. We choose: wait on ev_join for correctness.)

    cudaStreamWaitEvent(0, ev_join, 0);

    // GCN layer 0
    k_gemm64<<<gRows, T>>>(x, gcn_W0, p_xw, 1);
    k_agg<<<gAgg, T>>>(gcn_b0, bn_g0, bn_b0, bn_m0, bn_v0);

    // GCN layer 1
    k_gemm64<<<gRows, T>>>(p_agg, gcn_W1, p_xw, 1);
    k_agg<<<gAgg, T>>>(gcn_b1, bn_g1, bn_b1, bn_m1, bn_v1);

    // pool
    k_pool<<<gPool, 64>>>(batch);

    // MLP head
    k_mlp<<<NUM_GRAPHS, 256>>>(hW1, hb1, hg1, hbb1, hm1, hv1,
                               hW2, hb2, hg2, hbb2, hm2, hv2,
                               hW3, hb3, hW4, hb4, out);
}